// round 8
// baseline (speedup 1.0000x reference)
#include <cuda_runtime.h>
#include <cuda_bf16.h>
#include <cstdint>
#include <math.h>

#define B_      4
#define T_      4096
#define HID_    768
#define H_      12
#define D_      64
#define BH_     48
#define NBUCK_  32
#define NBTOT_  64
#define TOTAL_  8192
#define NCH_    64
#define CL_     128
#define M_      (B_*T_)      // 16384
#define PADK    65

// ---------------- scratch (static device globals; no allocation) ----------------
__device__ float g_qk[BH_*T_*D_];            // [bh][t][d]
__device__ float g_v [BH_*T_*D_];
__device__ int   g_bucket[BH_*TOTAL_];
__device__ int   g_sidx[BH_*TOTAL_];
__device__ int   g_undo[BH_*TOTAL_];
__device__ int   g_bbase[BH_*NBTOT_];
__device__ float g_so  [BH_*TOTAL_*D_];
__device__ float g_slog[BH_*TOTAL_];
__device__ float g_attn[M_*HID_];
__device__ float g_tmp [M_*HID_];

__device__ __forceinline__ unsigned int smem_u32(const void* p) {
    unsigned int a;
    asm("{ .reg .u64 t; cvta.to.shared.u64 t, %1; cvt.u32.u64 %0, t; }" : "=r"(a) : "l"(p));
    return a;
}
__device__ __forceinline__ void ldm_x4(unsigned int& r0, unsigned int& r1,
                                       unsigned int& r2, unsigned int& r3,
                                       unsigned int addr) {
    asm volatile("ldmatrix.sync.aligned.m8n8.x4.shared.b16 {%0,%1,%2,%3}, [%4];"
                 : "=r"(r0), "=r"(r1), "=r"(r2), "=r"(r3) : "r"(addr));
}
__device__ __forceinline__ void mma_bf16(float& c0, float& c1, float& c2, float& c3,
                                         unsigned int a0, unsigned int a1,
                                         unsigned int a2, unsigned int a3,
                                         unsigned int b0, unsigned int b1) {
    asm volatile("mma.sync.aligned.m16n8k16.row.col.f32.bf16.bf16.f32 "
                 "{%0,%1,%2,%3}, {%4,%5,%6,%7}, {%8,%9}, {%0,%1,%2,%3};"
                 : "+f"(c0), "+f"(c1), "+f"(c2), "+f"(c3)
                 : "r"(a0), "r"(a1), "r"(a2), "r"(a3), "r"(b0), "r"(b1));
}

// ================= split-bf16 GEMM via mma.sync (HMMA) =================
// C[M,768] = A[M,768] @ W[768,768]^T (+bias)
// block tile M=128, N=64, K-chunk=32; warp tile 32x32; 8 warps
// ns=2 -> 3 passes (~1e-5), ns=3 -> 6 passes (~1e-8)
// inmode:  0=Ain param, 1=g_attn, 2=g_tmp
// outmode: 0=Cout(+bias), 3=g_tmp(+bias), 1=g_qk merged-head, 2=g_v merged-head
#define LDA_ 40                      // halves per row (80B stride, ldmatrix conflict-free)
#define A_SPLIT_H (128*LDA_)         // 5120 halves = 10240 B
#define B_SPLIT_H (64*LDA_)          // 2560 halves = 5120 B
#define GEMM_SMEM_BYTES ((3*A_SPLIT_H + 3*B_SPLIT_H)*2)   // 46080

__global__ __launch_bounds__(256) void mma_gemm_kernel(
    const float* __restrict__ Ain, const float* __restrict__ W,
    const float* __restrict__ bias, float* __restrict__ Cout,
    int inmode, int outmode, int ns)
{
    extern __shared__ char smem[];
    const float* A = (inmode == 0) ? Ain : (inmode == 1 ? (const float*)g_attn : (const float*)g_tmp);
    __nv_bfloat16* As = (__nv_bfloat16*)smem;          // 3 splits of [128][LDA_]
    __nv_bfloat16* Bs = As + 3*A_SPLIT_H;              // 3 splits of [64][LDA_]
    unsigned int sA = smem_u32(As);
    unsigned int sB = smem_u32(Bs);

    int tid = threadIdx.x, wid = tid >> 5, lane = tid & 31;
    int bm = blockIdx.y * 128, bn = blockIdx.x * 64;
    int wm = (wid & 3) * 32;     // warp m offset in tile
    int wn = (wid >> 2) * 32;    // warp n offset in tile

    const int np = (ns == 2) ? 3 : 6;
    const int PA[6] = {0, 0, 1, 1, 0, 2};
    const int PB[6] = {0, 1, 0, 1, 2, 0};

    float acc[2][4][4];
#pragma unroll
    for (int mi = 0; mi < 2; mi++)
#pragma unroll
        for (int ni = 0; ni < 4; ni++)
#pragma unroll
            for (int q = 0; q < 4; q++) acc[mi][ni][q] = 0.f;

    // ldmatrix per-lane address offsets (halves), before k/pass offsets
    int ra  = (lane & 7) + ((lane >> 3) & 1) * 8;      // A row within 16
    int aco = (lane >> 4) * 8;                         // A col 8-group
    unsigned int aoff[2];
#pragma unroll
    for (int mi = 0; mi < 2; mi++)
        aoff[mi] = (unsigned int)((wm + mi*16 + ra) * LDA_ + aco);
    int rb  = lane & 7;
    int bco = ((lane >> 3) & 1) * 8;                   // B k8-group
    unsigned int boff[2];
#pragma unroll
    for (int g = 0; g < 2; g++)
        boff[g] = (unsigned int)((wn + (g*2 + (lane >> 4))*8 + rb) * LDA_ + bco);

    for (int kc = 0; kc < 24; kc++) {
        int k0 = kc * 32;
        __syncthreads();   // previous compute done -> smem reusable

        // ---- stage A tile 128x32 as ns bf16 splits ----
#pragma unroll
        for (int it = 0; it < 4; it++) {
            int i = tid + it * 256;           // 0..1023
            int row = i >> 3, qc = i & 7;     // col quad
            float4 v = *(const float4*)(A + (size_t)(bm + row) * HID_ + k0 + qc * 4);
            int hoff = row * LDA_ + qc * 4;
            float rx = v.x, ry = v.y, rz = v.z, rw = v.w;
            for (int s = 0; s < ns; s++) {
                __nv_bfloat16 bx = __float2bfloat16(rx), by = __float2bfloat16(ry);
                __nv_bfloat16 bz = __float2bfloat16(rz), bw = __float2bfloat16(rw);
                rx -= __bfloat162float(bx); ry -= __bfloat162float(by);
                rz -= __bfloat162float(bz); rw -= __bfloat162float(bw);
                uint2 u;
                u.x = (unsigned int)__bfloat16_as_ushort(bx) | ((unsigned int)__bfloat16_as_ushort(by) << 16);
                u.y = (unsigned int)__bfloat16_as_ushort(bz) | ((unsigned int)__bfloat16_as_ushort(bw) << 16);
                *(uint2*)(As + s * A_SPLIT_H + hoff) = u;
            }
        }
        // ---- stage B tile 64x32 ----
#pragma unroll
        for (int it = 0; it < 2; it++) {
            int i = tid + it * 256;           // 0..511
            int row = i >> 3, qc = i & 7;
            float4 v = *(const float4*)(W + (size_t)(bn + row) * HID_ + k0 + qc * 4);
            int hoff = row * LDA_ + qc * 4;
            float rx = v.x, ry = v.y, rz = v.z, rw = v.w;
            for (int s = 0; s < ns; s++) {
                __nv_bfloat16 bx = __float2bfloat16(rx), by = __float2bfloat16(ry);
                __nv_bfloat16 bz = __float2bfloat16(rz), bw = __float2bfloat16(rw);
                rx -= __bfloat162float(bx); ry -= __bfloat162float(by);
                rz -= __bfloat162float(bz); rw -= __bfloat162float(bw);
                uint2 u;
                u.x = (unsigned int)__bfloat16_as_ushort(bx) | ((unsigned int)__bfloat16_as_ushort(by) << 16);
                u.y = (unsigned int)__bfloat16_as_ushort(bz) | ((unsigned int)__bfloat16_as_ushort(bw) << 16);
                *(uint2*)(Bs + s * B_SPLIT_H + hoff) = u;
            }
        }
        __syncthreads();

        // ---- compute: np passes x 2 k16-steps x 8 mma ----
        for (int p = 0; p < np; p++) {
            unsigned int pa = sA + (unsigned int)(PA[p] * A_SPLIT_H * 2);
            unsigned int pb = sB + (unsigned int)(PB[p] * B_SPLIT_H * 2);
#pragma unroll
            for (int k16 = 0; k16 < 2; k16++) {
                unsigned int kb = (unsigned int)(k16 * 16 * 2);   // bytes
                unsigned int a[2][4], b[2][4];
#pragma unroll
                for (int mi = 0; mi < 2; mi++)
                    ldm_x4(a[mi][0], a[mi][1], a[mi][2], a[mi][3], pa + aoff[mi]*2 + kb);
#pragma unroll
                for (int g = 0; g < 2; g++)
                    ldm_x4(b[g][0], b[g][1], b[g][2], b[g][3], pb + boff[g]*2 + kb);
#pragma unroll
                for (int mi = 0; mi < 2; mi++) {
#pragma unroll
                    for (int ni = 0; ni < 4; ni++) {
                        unsigned int b0 = b[ni >> 1][(ni & 1) * 2];
                        unsigned int b1 = b[ni >> 1][(ni & 1) * 2 + 1];
                        mma_bf16(acc[mi][ni][0], acc[mi][ni][1], acc[mi][ni][2], acc[mi][ni][3],
                                 a[mi][0], a[mi][1], a[mi][2], a[mi][3], b0, b1);
                    }
                }
            }
        }
    }

    // ---- epilogue ----
#pragma unroll
    for (int mi = 0; mi < 2; mi++) {
#pragma unroll
        for (int ni = 0; ni < 4; ni++) {
            int r0 = bm + wm + mi*16 + (lane >> 2);
            int cc = wn + ni*8 + (lane & 3)*2;       // col within 64-wide tile
            float b0 = 0.f, b1 = 0.f;
            if (outmode == 0 || outmode == 3) { b0 = bias[bn+cc]; b1 = bias[bn+cc+1]; }
            float2 o0 = make_float2(acc[mi][ni][0] + b0, acc[mi][ni][1] + b1);
            float2 o1 = make_float2(acc[mi][ni][2] + b0, acc[mi][ni][3] + b1);
            if (outmode == 0 || outmode == 3) {
                float* dst = (outmode == 0) ? Cout : g_tmp;
                *(float2*)(dst + (size_t)r0     * HID_ + bn + cc) = o0;
                *(float2*)(dst + (size_t)(r0+8) * HID_ + bn + cc) = o1;
            } else {
                float* dst = (outmode == 1) ? g_qk : g_v;
                int h = bn >> 6;
                int b_0 = r0 >> 12, t_0 = r0 & (T_-1);
                int b_1 = (r0+8) >> 12, t_1 = (r0+8) & (T_-1);
                *(float2*)(dst + ((size_t)(b_0 * H_ + h) * T_ + t_0) * D_ + cc) = o0;
                *(float2*)(dst + ((size_t)(b_1 * H_ + h) * T_ + t_1) * D_ + cc) = o1;
            }
        }
    }
}

// ---------------- LSH bucketing: warp per (bh, t) ----------------
__global__ __launch_bounds__(256) void bucket_kernel(const float* __restrict__ rot)
{
    __shared__ float srot[D_ * 32];
    int tid = threadIdx.x;
    for (int i = tid; i < D_ * 32; i += 256) srot[i] = rot[i];
    __syncthreads();

    int lane = tid & 31;
    int wid  = tid >> 5;
    int row  = blockIdx.x * 8 + wid;
    int bh   = row >> 12;
    int t    = row & (T_-1);

    const float* q = g_qk + ((size_t)bh * T_ + t) * D_;
    float q0 = q[lane], q1 = q[lane + 32];
    float r = 0.f;
#pragma unroll
    for (int d = 0; d < 32; d++)
        r = fmaf(__shfl_sync(0xffffffffu, q0, d), srot[d * 32 + lane], r);
#pragma unroll
    for (int d = 0; d < 32; d++)
        r = fmaf(__shfl_sync(0xffffffffu, q1, d), srot[(d + 32) * 32 + lane], r);

    int i = lane & 15;
    float nr = -r;
    float v; int idx;
    if (r >= nr) { v = r;  idx = i; } else { v = nr; idx = i + 16; }
#pragma unroll
    for (int off = 8; off > 0; off >>= 1) {
        float ov = __shfl_down_sync(0xffffffffu, v,   off, 16);
        int   oi = __shfl_down_sync(0xffffffffu, idx, off, 16);
        if (ov > v || (ov == v && oi < idx)) { v = ov; idx = oi; }
    }
    if (i == 0) {
        int hash = lane >> 4;
        g_bucket[bh * TOTAL_ + hash * T_ + t] = idx + hash * NBUCK_;
    }
}

// ---------------- histogram + exclusive scan per bh ----------------
__global__ __launch_bounds__(256) void hist_kernel()
{
    __shared__ int h[NBTOT_];
    int bh = blockIdx.x;
    int tid = threadIdx.x;
    if (tid < NBTOT_) h[tid] = 0;
    __syncthreads();
    const int* bp = g_bucket + bh * TOTAL_;
    for (int j = tid; j < TOTAL_; j += 256) atomicAdd(&h[bp[j]], 1);
    __syncthreads();
    if (tid == 0) {
        int run = 0;
        for (int b = 0; b < NBTOT_; b++) { g_bbase[bh * NBTOT_ + b] = run; run += h[b]; }
    }
}

// ---------------- stable scatter: one block per (bucket, bh) ----------------
__global__ __launch_bounds__(256) void scatter_kernel()
{
    int bh  = blockIdx.y;
    int myb = blockIdx.x;
    int tid = threadIdx.x;
    const int* bp = g_bucket + bh * TOTAL_;
    int j0 = tid * 32;
    int cnt = 0;
    for (int k = 0; k < 32; k++) cnt += (bp[j0 + k] == myb);

    __shared__ int s[256];
    s[tid] = cnt;
    __syncthreads();
    for (int off = 1; off < 256; off <<= 1) {
        int v = (tid >= off) ? s[tid - off] : 0;
        __syncthreads();
        s[tid] += v;
        __syncthreads();
    }
    int pos = g_bbase[bh * NBTOT_ + myb] + s[tid] - cnt;
    for (int k = 0; k < 32; k++) {
        int j = j0 + k;
        if (bp[j] == myb) {
            g_sidx[bh * TOTAL_ + pos] = j;
            g_undo[bh * TOTAL_ + j]   = pos;
            pos++;
        }
    }
}

// ---------------- chunked LSH attention: one block per (chunk, bh) ----------------
#define ATTN_SMEM_FLOATS (128*PADK + 256*PADK + 256*PADK + 8*16*PADK)
#define ATTN_SMEM_BYTES  (ATTN_SMEM_FLOATS*4 + (128+256+128+256)*4)

__global__ __launch_bounds__(256, 1) void attn_kernel(const float* __restrict__ mask)
{
    extern __shared__ float smem_f[];
    float* sq = smem_f;
    float* sk = sq + 128*PADK;
    float* sv = sk + 256*PADK;
    float* sp = sv + 256*PADK;
    int*   tq = (int*)(sp + 8*16*PADK);
    int*   tk = tq + 128;
    int*   mq = tk + 256;
    int*   mk = mq + 128;

    int c   = blockIdx.x;
    int bh  = blockIdx.y;
    int tid = threadIdx.x;
    int base = bh * TOTAL_;
    const float* mrow = mask + (bh / H_) * T_;

    if (tid < 128) {
        int si = g_sidx[base + c * CL_ + tid];
        int tp = si & (T_-1);
        tq[tid] = tp;
        mq[tid] = (mrow[tp] != 0.f);
    }
    {
        int j  = tid;
        int cp = (c + NCH_ - 1) & (NCH_ - 1);
        int spos = (j < CL_) ? (c * CL_ + j) : (cp * CL_ + (j - CL_));
        int si = g_sidx[base + spos];
        int tp = si & (T_-1);
        tk[j] = tp;
        mk[j] = (mrow[tp] != 0.f);
    }
    __syncthreads();

    const float* qkb = g_qk + (size_t)bh * T_ * D_;
    const float* vb  = g_v  + (size_t)bh * T_ * D_;
    for (int idx = tid; idx < 128 * 64; idx += 256) {
        int r = idx >> 6, d = idx & 63;
        sq[r * PADK + d] = qkb[(size_t)tq[r] * D_ + d];
    }
    for (int idx = tid; idx < 256 * 64; idx += 256) {
        int r = idx >> 6, d = idx & 63;
        sk[r * PADK + d] = qkb[(size_t)tk[r] * D_ + d];
        sv[r * PADK + d] =  vb[(size_t)tk[r] * D_ + d];
    }
    __syncthreads();
    {
        int r = tid;
        float ss = 0.f;
#pragma unroll 8
        for (int d = 0; d < 64; d++) { float x = sk[r*PADK + d]; ss = fmaf(x, x, ss); }
        float inv = 1.f / fmaxf(sqrtf(ss), 1e-12f);
#pragma unroll 8
        for (int d = 0; d < 64; d++) sk[r*PADK + d] *= inv;
    }
    __syncthreads();

    int w = tid >> 5, lane = tid & 31;
    int rr = lane & 3, kk = lane >> 2;
    float* spw = sp + w * 16 * PADK;
    int rbase = w * 16 + rr;

    float m_[4], l_[4], oacc[4][8];
#pragma unroll
    for (int u = 0; u < 4; u++) {
        m_[u] = -INFINITY; l_[u] = 0.f;
#pragma unroll
        for (int v = 0; v < 8; v++) oacc[u][v] = 0.f;
    }
    int tqr[4], mqr[4];
#pragma unroll
    for (int u = 0; u < 4; u++) { tqr[u] = tq[rbase + 4*u]; mqr[u] = mq[rbase + 4*u]; }

    for (int tt = 0; tt < 4; tt++) {
        int jb = tt * 64;
        float dots[4][8];
#pragma unroll
        for (int u = 0; u < 4; u++)
#pragma unroll
            for (int s = 0; s < 8; s++) dots[u][s] = 0.f;

        for (int d = 0; d < 64; d++) {
            float qv[4];
#pragma unroll
            for (int u = 0; u < 4; u++) qv[u] = sq[(rbase + 4*u) * PADK + d];
#pragma unroll
            for (int s = 0; s < 8; s++) {
                float kv = sk[(jb + kk + 8*s) * PADK + d];
#pragma unroll
                for (int u = 0; u < 4; u++) dots[u][s] = fmaf(qv[u], kv, dots[u][s]);
            }
        }

        float tmax[4];
#pragma unroll
        for (int u = 0; u < 4; u++) {
            float mx = -INFINITY;
#pragma unroll
            for (int s = 0; s < 8; s++) {
                int j = jb + kk + 8*s;
                float val = dots[u][s] * 0.125f;
                if (!(mqr[u] && mk[j])) val = -1e9f;
                if (tqr[u] == tk[j])    val = -5e4f;
                dots[u][s] = val;
                mx = fmaxf(mx, val);
            }
            tmax[u] = mx;
        }
#pragma unroll
        for (int off = 4; off < 32; off <<= 1)
#pragma unroll
            for (int u = 0; u < 4; u++)
                tmax[u] = fmaxf(tmax[u], __shfl_xor_sync(0xffffffffu, tmax[u], off));

        float corr[4], lsum[4];
#pragma unroll
        for (int u = 0; u < 4; u++) {
            float mn = fmaxf(m_[u], tmax[u]);
            corr[u] = __expf(m_[u] - mn);
            m_[u] = mn;
            float sloc = 0.f;
#pragma unroll
            for (int s = 0; s < 8; s++) {
                float p = __expf(dots[u][s] - mn);
                dots[u][s] = p;
                sloc += p;
            }
            lsum[u] = sloc;
        }
#pragma unroll
        for (int off = 4; off < 32; off <<= 1)
#pragma unroll
            for (int u = 0; u < 4; u++)
                lsum[u] += __shfl_xor_sync(0xffffffffu, lsum[u], off);
#pragma unroll
        for (int u = 0; u < 4; u++) {
            l_[u] = l_[u] * corr[u] + lsum[u];
#pragma unroll
            for (int v = 0; v < 8; v++) oacc[u][v] *= corr[u];
#pragma unroll
            for (int s = 0; s < 8; s++) spw[(rr + 4*u) * PADK + kk + 8*s] = dots[u][s];
        }
        __syncwarp();

        for (int jl = 0; jl < 64; jl++) {
            float pv[4];
#pragma unroll
            for (int u = 0; u < 4; u++) pv[u] = spw[(rr + 4*u) * PADK + jl];
            float vvr[8];
#pragma unroll
            for (int v = 0; v < 8; v++) vvr[v] = sv[(jb + jl) * PADK + kk + 8*v];
#pragma unroll
            for (int u = 0; u < 4; u++)
#pragma unroll
                for (int v = 0; v < 8; v++)
                    oacc[u][v] = fmaf(pv[u], vvr[v], oacc[u][v]);
        }
        __syncwarp();
    }

#pragma unroll
    for (int u = 0; u < 4; u++) {
        int r  = rbase + 4*u;
        int gp = base + c * CL_ + r;
        float inv = 1.f / l_[u];
        if (kk == 0) g_slog[gp] = m_[u] + logf(l_[u]);
#pragma unroll
        for (int v = 0; v < 8; v++)
            g_so[(size_t)gp * D_ + kk + 8*v] = oacc[u][v] * inv;
    }
}

// ---------------- unsort + combine hash rounds ----------------
__global__ __launch_bounds__(256) void combine_kernel()
{
    int idx  = blockIdx.x * 256 + threadIdx.x;
    int d    = idx & 63;
    int rowi = idx >> 6;
    int t    = rowi & (T_-1);
    int bh   = rowi >> 12;
    int b = bh / H_, h = bh % H_;
    int p0 = g_undo[bh * TOTAL_ + t];
    int p1 = g_undo[bh * TOTAL_ + T_ + t];
    float l0 = g_slog[bh * TOTAL_ + p0];
    float l1 = g_slog[bh * TOTAL_ + p1];
    float mm = fmaxf(l0, l1);
    float w0 = __expf(l0 - mm), w1 = __expf(l1 - mm);
    float inv = 1.f / (w0 + w1);
    float o0 = g_so[((size_t)(bh * TOTAL_ + p0)) * D_ + d];
    float o1 = g_so[((size_t)(bh * TOTAL_ + p1)) * D_ + d];
    g_attn[((size_t)(b * T_ + t)) * HID_ + h * D_ + d] = (w0 * o0 + w1 * o1) * inv;
}

// ---------------- launcher ----------------
extern "C" void kernel_launch(void* const* d_in, const int* in_sizes, int n_in,
                              void* d_out, int out_size)
{
    const float* X    = (const float*)d_in[0];
    const float* mask = (const float*)d_in[1];
    const float* W_qk = (const float*)d_in[2];
    const float* W_v  = (const float*)d_in[3];
    const float* rot  = (const float*)d_in[4];
    const float* W_to = (const float*)d_in[5];
    const float* b_to = (const float*)d_in[6];
    const float* W_o  = (const float*)d_in[7];
    const float* b_o  = (const float*)d_in[8];
    float* out = (float*)d_out;

    cudaFuncSetAttribute(mma_gemm_kernel, cudaFuncAttributeMaxDynamicSharedMemorySize, GEMM_SMEM_BYTES);
    cudaFuncSetAttribute(attn_kernel,     cudaFuncAttributeMaxDynamicSharedMemorySize, ATTN_SMEM_BYTES);

    dim3 gg(HID_ / 64, M_ / 128);   // (12, 128)

    // QK projection: 3-way split (exact buckets), V: 2-way split
    mma_gemm_kernel<<<gg, 256, GEMM_SMEM_BYTES>>>(X, W_qk, nullptr, nullptr, 0, 1, 3);
    mma_gemm_kernel<<<gg, 256, GEMM_SMEM_BYTES>>>(X, W_v,  nullptr, nullptr, 0, 2, 2);

    bucket_kernel<<<(BH_ * T_) / 8, 256>>>(rot);
    hist_kernel<<<BH_, 256>>>();
    scatter_kernel<<<dim3(NBTOT_, BH_), 256>>>();

    attn_kernel<<<dim3(NCH_, BH_), 256, ATTN_SMEM_BYTES>>>(mask);

    combine_kernel<<<(BH_ * T_ * D_) / 256, 256>>>();

    mma_gemm_kernel<<<gg, 256, GEMM_SMEM_BYTES>>>(nullptr, W_to, b_to, nullptr, 1, 3, 2);
    mma_gemm_kernel<<<gg, 256, GEMM_SMEM_BYTES>>>(nullptr, W_o,  b_o,  out,     2, 0, 2);
}

// round 10
// speedup vs baseline: 1.3466x; 1.3466x over previous
#include <cuda_runtime.h>
#include <cuda_bf16.h>
#include <cstdint>
#include <math.h>

#define B_      4
#define T_      4096
#define HID_    768
#define H_      12
#define D_      64
#define BH_     48
#define NBUCK_  32
#define NBTOT_  64
#define TOTAL_  8192
#define NCH_    64
#define CL_     128
#define M_      (B_*T_)      // 16384
#define PADK    65

// ---------------- scratch (static device globals; no allocation) ----------------
__device__ float g_qk[BH_*T_*D_];            // [bh][t][d]
__device__ float g_v [BH_*T_*D_];
__device__ int   g_bucket[BH_*TOTAL_];
__device__ int   g_sidx[BH_*TOTAL_];
__device__ int   g_undo[BH_*TOTAL_];
__device__ int   g_bbase[BH_*NBTOT_];
__device__ float g_so  [BH_*TOTAL_*D_];
__device__ float g_slog[BH_*TOTAL_];
__device__ float g_attn[M_*HID_];
__device__ float g_tmp [M_*HID_];
// bf16 split planes: A-side (16384x768 per split), B-side (768x768 per split)
__device__ __nv_bfloat16 g_as[3 * M_ * HID_];
__device__ __nv_bfloat16 g_bs[3 * HID_ * HID_];

__device__ __forceinline__ unsigned int smem_u32(const void* p) {
    unsigned int a;
    asm("{ .reg .u64 t; cvta.to.shared.u64 t, %1; cvt.u32.u64 %0, t; }" : "=r"(a) : "l"(p));
    return a;
}
__device__ __forceinline__ void ldm_x4(unsigned int& r0, unsigned int& r1,
                                       unsigned int& r2, unsigned int& r3,
                                       unsigned int addr) {
    asm volatile("ldmatrix.sync.aligned.m8n8.x4.shared.b16 {%0,%1,%2,%3}, [%4];"
                 : "=r"(r0), "=r"(r1), "=r"(r2), "=r"(r3) : "r"(addr));
}
__device__ __forceinline__ void mma_bf16(float& c0, float& c1, float& c2, float& c3,
                                         unsigned int a0, unsigned int a1,
                                         unsigned int a2, unsigned int a3,
                                         unsigned int b0, unsigned int b1) {
    asm volatile("mma.sync.aligned.m16n8k16.row.col.f32.bf16.bf16.f32 "
                 "{%0,%1,%2,%3}, {%4,%5,%6,%7}, {%8,%9}, {%0,%1,%2,%3};"
                 : "+f"(c0), "+f"(c1), "+f"(c2), "+f"(c3)
                 : "r"(a0), "r"(a1), "r"(a2), "r"(a3), "r"(b0), "r"(b1));
}
__device__ __forceinline__ void cp8(unsigned int dst, const void* src) {
    asm volatile("cp.async.ca.shared.global [%0], [%1], 8;" :: "r"(dst), "l"(src));
}
__device__ __forceinline__ void cp_commit() {
    asm volatile("cp.async.commit_group;" ::: "memory");
}

// ---------------- fp32 -> ns bf16 split planes ----------------
// which: 0 -> g_as, 1 -> g_bs     insel: 0 -> src param, 1 -> g_attn, 2 -> g_tmp
__global__ __launch_bounds__(256) void split_kernel(const float* __restrict__ srcp,
                                                    int n4, int ns, int which, int insel)
{
    int idx = blockIdx.x * 256 + threadIdx.x;
    if (idx >= n4) return;
    const float* src = (insel == 0) ? srcp : (insel == 1 ? (const float*)g_attn : (const float*)g_tmp);
    float4 v = ((const float4*)src)[idx];
    __nv_bfloat16* dst = which ? g_bs : g_as;
    size_t stride = which ? (size_t)HID_ * HID_ : (size_t)M_ * HID_;
    float rx = v.x, ry = v.y, rz = v.z, rw = v.w;
    for (int s = 0; s < ns; s++) {
        __nv_bfloat16 bx = __float2bfloat16(rx), by = __float2bfloat16(ry);
        __nv_bfloat16 bz = __float2bfloat16(rz), bw = __float2bfloat16(rw);
        rx -= __bfloat162float(bx); ry -= __bfloat162float(by);
        rz -= __bfloat162float(bz); rw -= __bfloat162float(bw);
        uint2 u;
        u.x = (unsigned int)__bfloat16_as_ushort(bx) | ((unsigned int)__bfloat16_as_ushort(by) << 16);
        u.y = (unsigned int)__bfloat16_as_ushort(bz) | ((unsigned int)__bfloat16_as_ushort(bw) << 16);
        *(uint2*)(dst + s * stride + (size_t)idx * 4) = u;
    }
}

// ================= split-bf16 GEMM via mma.sync + cp.async pipeline =================
// C[M,768] = A[M,768] @ W[768,768]^T (+bias), A/B pre-split in g_as/g_bs
// block tile M=128, N=64, K-chunk=32; warp tile 32x32; 8 warps; 2-stage cp.async
// outmode: 0=Cout(+bias), 3=g_tmp(+bias), 1=g_qk merged-head, 2=g_v merged-head
#define LDA_ 40                      // halves per row (80B stride, ldmatrix conflict-free)
#define A_SP_H (128*LDA_)            // 5120 halves
#define B_SP_H (64*LDA_)             // 2560 halves
#define STAGE_H (3*A_SP_H + 3*B_SP_H)
#define STAGE_B (STAGE_H*2)          // 46080
#define GEMM_SMEM_BYTES (2*STAGE_B)  // 92160

__global__ __launch_bounds__(256) void mma_gemm_kernel(
    const float* __restrict__ bias, float* __restrict__ Cout,
    int outmode, int ns)
{
    extern __shared__ char smem[];
    unsigned int sbase = smem_u32(smem);

    int tid = threadIdx.x, wid = tid >> 5, lane = tid & 31;
    int bm = blockIdx.y * 128, bn = blockIdx.x * 64;
    int wm = (wid & 3) * 32;
    int wn = (wid >> 2) * 32;

    const int np = (ns == 2) ? 3 : 6;
    const int PA[6] = {0, 0, 1, 1, 0, 2};
    const int PB[6] = {0, 1, 0, 1, 2, 0};

    float acc[2][4][4];
#pragma unroll
    for (int mi = 0; mi < 2; mi++)
#pragma unroll
        for (int ni = 0; ni < 4; ni++)
#pragma unroll
            for (int q = 0; q < 4; q++) acc[mi][ni][q] = 0.f;

    int arow = tid >> 3, aqc = tid & 7;
    int ra  = (lane & 7) + ((lane >> 3) & 1) * 8;
    int aco = (lane >> 4) * 8;
    unsigned int aoff[2];
#pragma unroll
    for (int mi = 0; mi < 2; mi++)
        aoff[mi] = (unsigned int)((wm + mi*16 + ra) * LDA_ + aco);
    int rb  = lane & 7;
    int bco = ((lane >> 3) & 1) * 8;
    unsigned int boff[2];
#pragma unroll
    for (int g = 0; g < 2; g++)
        boff[g] = (unsigned int)((wn + (g*2 + (lane >> 4))*8 + rb) * LDA_ + bco);

    const size_t ASZ = (size_t)M_ * HID_;
    const size_t BSZ = (size_t)HID_ * HID_;

    auto issue = [&](int kc, int buf) {
        int k0 = kc * 32;
        unsigned int sbuf = sbase + buf * STAGE_B;
        for (int s = 0; s < ns; s++) {
            const __nv_bfloat16* ga = g_as + s * ASZ + (size_t)(bm + arow) * HID_ + k0 + aqc * 4;
            unsigned int da = sbuf + (unsigned int)((s * A_SP_H + arow * LDA_ + aqc * 4) * 2);
#pragma unroll
            for (int i = 0; i < 4; i++)
                cp8(da + (unsigned int)(i * 32 * LDA_ * 2), ga + (size_t)i * 32 * HID_);
            const __nv_bfloat16* gb = g_bs + s * BSZ + (size_t)(bn + arow) * HID_ + k0 + aqc * 4;
            unsigned int db = sbuf + (unsigned int)((3 * A_SP_H + s * B_SP_H + arow * LDA_ + aqc * 4) * 2);
#pragma unroll
            for (int i = 0; i < 2; i++)
                cp8(db + (unsigned int)(i * 32 * LDA_ * 2), gb + (size_t)i * 32 * HID_);
        }
        cp_commit();
    };

    issue(0, 0);

    for (int kc = 0; kc < 24; kc++) {
        if (kc < 23) {
            issue(kc + 1, (kc + 1) & 1);
            asm volatile("cp.async.wait_group 1;" ::: "memory");
        } else {
            asm volatile("cp.async.wait_group 0;" ::: "memory");
        }
        __syncthreads();

        unsigned int sbuf = sbase + (kc & 1) * STAGE_B;
        for (int p = 0; p < np; p++) {
            unsigned int pa = sbuf + (unsigned int)(PA[p] * A_SP_H * 2);
            unsigned int pb = sbuf + (unsigned int)((3 * A_SP_H + PB[p] * B_SP_H) * 2);
#pragma unroll
            for (int k16 = 0; k16 < 2; k16++) {
                unsigned int kb = (unsigned int)(k16 * 16 * 2);
                unsigned int a[2][4], b[2][4];
#pragma unroll
                for (int mi = 0; mi < 2; mi++)
                    ldm_x4(a[mi][0], a[mi][1], a[mi][2], a[mi][3], pa + aoff[mi]*2 + kb);
#pragma unroll
                for (int g = 0; g < 2; g++)
                    ldm_x4(b[g][0], b[g][1], b[g][2], b[g][3], pb + boff[g]*2 + kb);
#pragma unroll
                for (int mi = 0; mi < 2; mi++) {
#pragma unroll
                    for (int ni = 0; ni < 4; ni++) {
                        unsigned int b0 = b[ni >> 1][(ni & 1) * 2];
                        unsigned int b1 = b[ni >> 1][(ni & 1) * 2 + 1];
                        mma_bf16(acc[mi][ni][0], acc[mi][ni][1], acc[mi][ni][2], acc[mi][ni][3],
                                 a[mi][0], a[mi][1], a[mi][2], a[mi][3], b0, b1);
                    }
                }
            }
        }
        __syncthreads();
    }

    // ---- epilogue ----
#pragma unroll
    for (int mi = 0; mi < 2; mi++) {
#pragma unroll
        for (int ni = 0; ni < 4; ni++) {
            int r0 = bm + wm + mi*16 + (lane >> 2);
            int cc = wn + ni*8 + (lane & 3)*2;
            float b0 = 0.f, b1 = 0.f;
            if (outmode == 0 || outmode == 3) { b0 = bias[bn+cc]; b1 = bias[bn+cc+1]; }
            float2 o0 = make_float2(acc[mi][ni][0] + b0, acc[mi][ni][1] + b1);
            float2 o1 = make_float2(acc[mi][ni][2] + b0, acc[mi][ni][3] + b1);
            if (outmode == 0 || outmode == 3) {
                float* dst = (outmode == 0) ? Cout : g_tmp;
                *(float2*)(dst + (size_t)r0     * HID_ + bn + cc) = o0;
                *(float2*)(dst + (size_t)(r0+8) * HID_ + bn + cc) = o1;
            } else {
                float* dst = (outmode == 1) ? g_qk : g_v;
                int h = bn >> 6;
                int b_0 = r0 >> 12, t_0 = r0 & (T_-1);
                int b_1 = (r0+8) >> 12, t_1 = (r0+8) & (T_-1);
                *(float2*)(dst + ((size_t)(b_0 * H_ + h) * T_ + t_0) * D_ + cc) = o0;
                *(float2*)(dst + ((size_t)(b_1 * H_ + h) * T_ + t_1) * D_ + cc) = o1;
            }
        }
    }
}

// ---------------- LSH bucketing: warp per (bh, t) ----------------
__global__ __launch_bounds__(256) void bucket_kernel(const float* __restrict__ rot)
{
    __shared__ float srot[D_ * 32];
    int tid = threadIdx.x;
    for (int i = tid; i < D_ * 32; i += 256) srot[i] = rot[i];
    __syncthreads();

    int lane = tid & 31;
    int wid  = tid >> 5;
    int row  = blockIdx.x * 8 + wid;
    int bh   = row >> 12;
    int t    = row & (T_-1);

    const float* q = g_qk + ((size_t)bh * T_ + t) * D_;
    float q0 = q[lane], q1 = q[lane + 32];
    float r = 0.f;
#pragma unroll
    for (int d = 0; d < 32; d++)
        r = fmaf(__shfl_sync(0xffffffffu, q0, d), srot[d * 32 + lane], r);
#pragma unroll
    for (int d = 0; d < 32; d++)
        r = fmaf(__shfl_sync(0xffffffffu, q1, d), srot[(d + 32) * 32 + lane], r);

    int i = lane & 15;
    float nr = -r;
    float v; int idx;
    if (r >= nr) { v = r;  idx = i; } else { v = nr; idx = i + 16; }
#pragma unroll
    for (int off = 8; off > 0; off >>= 1) {
        float ov = __shfl_down_sync(0xffffffffu, v,   off, 16);
        int   oi = __shfl_down_sync(0xffffffffu, idx, off, 16);
        if (ov > v || (ov == v && oi < idx)) { v = ov; idx = oi; }
    }
    if (i == 0) {
        int hash = lane >> 4;
        g_bucket[bh * TOTAL_ + hash * T_ + t] = idx + hash * NBUCK_;
    }
}

// ---------------- histogram + exclusive scan per bh ----------------
__global__ __launch_bounds__(256) void hist_kernel()
{
    __shared__ int h[NBTOT_];
    int bh = blockIdx.x;
    int tid = threadIdx.x;
    if (tid < NBTOT_) h[tid] = 0;
    __syncthreads();
    const int* bp = g_bucket + bh * TOTAL_;
    for (int j = tid; j < TOTAL_; j += 256) atomicAdd(&h[bp[j]], 1);
    __syncthreads();
    if (tid == 0) {
        int run = 0;
        for (int b = 0; b < NBTOT_; b++) { g_bbase[bh * NBTOT_ + b] = run; run += h[b]; }
    }
}

// ---------------- stable scatter: one block per (bucket, bh) ----------------
__global__ __launch_bounds__(256) void scatter_kernel()
{
    int bh  = blockIdx.y;
    int myb = blockIdx.x;
    int tid = threadIdx.x;
    const int* bp = g_bucket + bh * TOTAL_;
    int j0 = tid * 32;
    int cnt = 0;
    for (int k = 0; k < 32; k++) cnt += (bp[j0 + k] == myb);

    __shared__ int s[256];
    s[tid] = cnt;
    __syncthreads();
    for (int off = 1; off < 256; off <<= 1) {
        int v = (tid >= off) ? s[tid - off] : 0;
        __syncthreads();
        s[tid] += v;
        __syncthreads();
    }
    int pos = g_bbase[bh * NBTOT_ + myb] + s[tid] - cnt;
    for (int k = 0; k < 32; k++) {
        int j = j0 + k;
        if (bp[j] == myb) {
            g_sidx[bh * TOTAL_ + pos] = j;
            g_undo[bh * TOTAL_ + j]   = pos;
            pos++;
        }
    }
}

// ---------------- chunked LSH attention: one block per (chunk, bh) ----------------
#define ATTN_SMEM_FLOATS (128*PADK + 256*PADK + 256*PADK + 8*16*PADK)
#define ATTN_SMEM_BYTES  (ATTN_SMEM_FLOATS*4 + (128+256+128+256)*4)

__global__ __launch_bounds__(256, 1) void attn_kernel(const float* __restrict__ mask)
{
    extern __shared__ float smem_f[];
    float* sq = smem_f;
    float* sk = sq + 128*PADK;
    float* sv = sk + 256*PADK;
    float* sp = sv + 256*PADK;
    int*   tq = (int*)(sp + 8*16*PADK);
    int*   tk = tq + 128;
    int*   mq = tk + 256;
    int*   mk = mq + 128;

    int c   = blockIdx.x;
    int bh  = blockIdx.y;
    int tid = threadIdx.x;
    int base = bh * TOTAL_;
    const float* mrow = mask + (bh / H_) * T_;

    if (tid < 128) {
        int si = g_sidx[base + c * CL_ + tid];
        int tp = si & (T_-1);
        tq[tid] = tp;
        mq[tid] = (mrow[tp] != 0.f);
    }
    {
        int j  = tid;
        int cp = (c + NCH_ - 1) & (NCH_ - 1);
        int spos = (j < CL_) ? (c * CL_ + j) : (cp * CL_ + (j - CL_));
        int si = g_sidx[base + spos];
        int tp = si & (T_-1);
        tk[j] = tp;
        mk[j] = (mrow[tp] != 0.f);
    }
    __syncthreads();

    const float* qkb = g_qk + (size_t)bh * T_ * D_;
    const float* vb  = g_v  + (size_t)bh * T_ * D_;
    for (int idx = tid; idx < 128 * 64; idx += 256) {
        int r = idx >> 6, d = idx & 63;
        sq[r * PADK + d] = qkb[(size_t)tq[r] * D_ + d];
    }
    for (int idx = tid; idx < 256 * 64; idx += 256) {
        int r = idx >> 6, d = idx & 63;
        sk[r * PADK + d] = qkb[(size_t)tk[r] * D_ + d];
        sv[r * PADK + d] =  vb[(size_t)tk[r] * D_ + d];
    }
    __syncthreads();
    {
        int r = tid;
        float ss = 0.f;
#pragma unroll 8
        for (int d = 0; d < 64; d++) { float x = sk[r*PADK + d]; ss = fmaf(x, x, ss); }
        float inv = 1.f / fmaxf(sqrtf(ss), 1e-12f);
#pragma unroll 8
        for (int d = 0; d < 64; d++) sk[r*PADK + d] *= inv;
    }
    __syncthreads();

    int w = tid >> 5, lane = tid & 31;
    int rr = lane & 3, kk = lane >> 2;
    float* spw = sp + w * 16 * PADK;
    int rbase = w * 16 + rr;

    float m_[4], l_[4], oacc[4][8];
#pragma unroll
    for (int u = 0; u < 4; u++) {
        m_[u] = -INFINITY; l_[u] = 0.f;
#pragma unroll
        for (int v = 0; v < 8; v++) oacc[u][v] = 0.f;
    }
    int tqr[4], mqr[4];
#pragma unroll
    for (int u = 0; u < 4; u++) { tqr[u] = tq[rbase + 4*u]; mqr[u] = mq[rbase + 4*u]; }

    for (int tt = 0; tt < 4; tt++) {
        int jb = tt * 64;
        float dots[4][8];
#pragma unroll
        for (int u = 0; u < 4; u++)
#pragma unroll
            for (int s = 0; s < 8; s++) dots[u][s] = 0.f;

        for (int d = 0; d < 64; d++) {
            float qv[4];
#pragma unroll
            for (int u = 0; u < 4; u++) qv[u] = sq[(rbase + 4*u) * PADK + d];
#pragma unroll
            for (int s = 0; s < 8; s++) {
                float kv = sk[(jb + kk + 8*s) * PADK + d];
#pragma unroll
                for (int u = 0; u < 4; u++) dots[u][s] = fmaf(qv[u], kv, dots[u][s]);
            }
        }

        float tmax[4];
#pragma unroll
        for (int u = 0; u < 4; u++) {
            float mx = -INFINITY;
#pragma unroll
            for (int s = 0; s < 8; s++) {
                int j = jb + kk + 8*s;
                float val = dots[u][s] * 0.125f;
                if (!(mqr[u] && mk[j])) val = -1e9f;
                if (tqr[u] == tk[j])    val = -5e4f;
                dots[u][s] = val;
                mx = fmaxf(mx, val);
            }
            tmax[u] = mx;
        }
#pragma unroll
        for (int off = 4; off < 32; off <<= 1)
#pragma unroll
            for (int u = 0; u < 4; u++)
                tmax[u] = fmaxf(tmax[u], __shfl_xor_sync(0xffffffffu, tmax[u], off));

        float corr[4], lsum[4];
#pragma unroll
        for (int u = 0; u < 4; u++) {
            float mn = fmaxf(m_[u], tmax[u]);
            corr[u] = __expf(m_[u] - mn);
            m_[u] = mn;
            float sloc = 0.f;
#pragma unroll
            for (int s = 0; s < 8; s++) {
                float p = __expf(dots[u][s] - mn);
                dots[u][s] = p;
                sloc += p;
            }
            lsum[u] = sloc;
        }
#pragma unroll
        for (int off = 4; off < 32; off <<= 1)
#pragma unroll
            for (int u = 0; u < 4; u++)
                lsum[u] += __shfl_xor_sync(0xffffffffu, lsum[u], off);
#pragma unroll
        for (int u = 0; u < 4; u++) {
            l_[u] = l_[u] * corr[u] + lsum[u];
#pragma unroll
            for (int v = 0; v < 8; v++) oacc[u][v] *= corr[u];
#pragma unroll
            for (int s = 0; s < 8; s++) spw[(rr + 4*u) * PADK + kk + 8*s] = dots[u][s];
        }
        __syncwarp();

        for (int jl = 0; jl < 64; jl++) {
            float pv[4];
#pragma unroll
            for (int u = 0; u < 4; u++) pv[u] = spw[(rr + 4*u) * PADK + jl];
            float vvr[8];
#pragma unroll
            for (int v = 0; v < 8; v++) vvr[v] = sv[(jb + jl) * PADK + kk + 8*v];
#pragma unroll
            for (int u = 0; u < 4; u++)
#pragma unroll
                for (int v = 0; v < 8; v++)
                    oacc[u][v] = fmaf(pv[u], vvr[v], oacc[u][v]);
        }
        __syncwarp();
    }

#pragma unroll
    for (int u = 0; u < 4; u++) {
        int r  = rbase + 4*u;
        int gp = base + c * CL_ + r;
        float inv = 1.f / l_[u];
        if (kk == 0) g_slog[gp] = m_[u] + logf(l_[u]);
#pragma unroll
        for (int v = 0; v < 8; v++)
            g_so[(size_t)gp * D_ + kk + 8*v] = oacc[u][v] * inv;
    }
}

// ---------------- unsort + combine hash rounds ----------------
__global__ __launch_bounds__(256) void combine_kernel()
{
    int idx  = blockIdx.x * 256 + threadIdx.x;
    int d    = idx & 63;
    int rowi = idx >> 6;
    int t    = rowi & (T_-1);
    int bh   = rowi >> 12;
    int b = bh / H_, h = bh % H_;
    int p0 = g_undo[bh * TOTAL_ + t];
    int p1 = g_undo[bh * TOTAL_ + T_ + t];
    float l0 = g_slog[bh * TOTAL_ + p0];
    float l1 = g_slog[bh * TOTAL_ + p1];
    float mm = fmaxf(l0, l1);
    float w0 = __expf(l0 - mm), w1 = __expf(l1 - mm);
    float inv = 1.f / (w0 + w1);
    float o0 = g_so[((size_t)(bh * TOTAL_ + p0)) * D_ + d];
    float o1 = g_so[((size_t)(bh * TOTAL_ + p1)) * D_ + d];
    g_attn[((size_t)(b * T_ + t)) * HID_ + h * D_ + d] = (w0 * o0 + w1 * o1) * inv;
}

// ---------------- launcher ----------------
extern "C" void kernel_launch(void* const* d_in, const int* in_sizes, int n_in,
                              void* d_out, int out_size)
{
    const float* X    = (const float*)d_in[0];
    const float* mask = (const float*)d_in[1];
    const float* W_qk = (const float*)d_in[2];
    const float* W_v  = (const float*)d_in[3];
    const float* rot  = (const float*)d_in[4];
    const float* W_to = (const float*)d_in[5];
    const float* b_to = (const float*)d_in[6];
    const float* W_o  = (const float*)d_in[7];
    const float* b_o  = (const float*)d_in[8];
    float* out = (float*)d_out;

    cudaFuncSetAttribute(mma_gemm_kernel, cudaFuncAttributeMaxDynamicSharedMemorySize, GEMM_SMEM_BYTES);
    cudaFuncSetAttribute(attn_kernel,     cudaFuncAttributeMaxDynamicSharedMemorySize, ATTN_SMEM_BYTES);

    const int NX4 = M_ * HID_ / 4;       // 3,145,728
    const int NW4 = HID_ * HID_ / 4;     // 147,456
    const int GX  = (NX4 + 255) / 256;
    const int GW  = (NW4 + 255) / 256;
    dim3 gg(HID_ / 64, M_ / 128);        // (12, 128)

    // --- QK projection: 3-way split (exact buckets) ---
    split_kernel<<<GX, 256>>>(X,    NX4, 3, 0, 0);
    split_kernel<<<GW, 256>>>(W_qk, NW4, 3, 1, 0);
    mma_gemm_kernel<<<gg, 256, GEMM_SMEM_BYTES>>>(nullptr, nullptr, 1, 3);   // -> g_qk
    // --- V projection: 2-way split (A splits 0,1 of X reused) ---
    split_kernel<<<GW, 256>>>(W_v,  NW4, 2, 1, 0);
    mma_gemm_kernel<<<gg, 256, GEMM_SMEM_BYTES>>>(nullptr, nullptr, 2, 2);   // -> g_v

    bucket_kernel<<<(BH_ * T_) / 8, 256>>>(rot);
    hist_kernel<<<BH_, 256>>>();
    scatter_kernel<<<dim3(NBTOT_, BH_), 256>>>();

    attn_kernel<<<dim3(NCH_, BH_), 256, ATTN_SMEM_BYTES>>>(mask);

    combine_kernel<<<(BH_ * T_ * D_) / 256, 256>>>();

    // --- W_to: 2-way split of attn output (device-resident, selected in-kernel) ---
    split_kernel<<<GX, 256>>>(nullptr, NX4, 2, 0, 1);
    split_kernel<<<GW, 256>>>(W_to,    NW4, 2, 1, 0);
    mma_gemm_kernel<<<gg, 256, GEMM_SMEM_BYTES>>>(b_to, nullptr, 3, 2);      // -> g_tmp
    // --- W_o: 2-way split of tmp ---
    split_kernel<<<GX, 256>>>(nullptr, NX4, 2, 0, 2);
    split_kernel<<<GW, 256>>>(W_o,     NW4, 2, 1, 0);
    mma_gemm_kernel<<<gg, 256, GEMM_SMEM_BYTES>>>(b_o, out, 0, 2);           // -> d_out
}